// round 1
// baseline (speedup 1.0000x reference)
#include <cuda_runtime.h>

#define Bsz 32
#define Tenc 400
#define Hd 512
#define Lsteps 100
#define Vout 511
#define KS 15

// ---------------- persistent state (device globals; no allocation) ----------
__device__ float g_hx[2][Bsz * Hd];   // ping-pong GRU hidden state
__device__ float g_sx[Bsz * Hd];      // attention context
__device__ float g_scores[Bsz * Tenc];

__device__ __forceinline__ float warp_sum(float v) {
    #pragma unroll
    for (int o = 16; o; o >>= 1) v += __shfl_xor_sync(0xffffffffu, v, o);
    return v;
}

// ---------------- zero initial hidden state ---------------------------------
__global__ void zero_hx_kernel() {
    g_hx[0][blockIdx.x * blockDim.x + threadIdx.x] = 0.0f;
}

// ---------------- K1: GRU cell (+ fc for previous step) ---------------------
// blocks [0,2048): GRU — block handles one b, 8 h outputs (1 warp each)
// blocks [2048,4096): fc for step t-1 (only when t>0) — one b, 8 v outputs
__global__ void k1_gru_fc(
    const int* __restrict__ y, const float* __restrict__ emb,
    const float* __restrict__ W_ih, const float* __restrict__ W_hh,
    const float* __restrict__ b_ih, const float* __restrict__ b_hh,
    const float* __restrict__ fc_w, const float* __restrict__ fc_b,
    float* __restrict__ out, int t, int rd, int wr)
{
    int blk = blockIdx.x;
    int tid = threadIdx.x;
    int w = tid >> 5, lane = tid & 31;

    if (blk < 2048) {
        __shared__ float s_ix[Hd];
        __shared__ float s_hx[Hd];
        int b = blk >> 6;
        int h0 = (blk & 63) << 3;
        int tok = y[b * 101 + t];
        for (int i = tid; i < Hd; i += 256) {
            float v = emb[tok * Hd + i];
            if (t > 0) v += g_sx[b * Hd + i];
            s_ix[i] = v;
            s_hx[i] = g_hx[rd][b * Hd + i];
        }
        __syncthreads();

        int h = h0 + w;
        const float* wi0 = W_ih + (size_t)h * Hd;
        const float* wi1 = W_ih + (size_t)(Hd + h) * Hd;
        const float* wi2 = W_ih + (size_t)(2 * Hd + h) * Hd;
        const float* wh0 = W_hh + (size_t)h * Hd;
        const float* wh1 = W_hh + (size_t)(Hd + h) * Hd;
        const float* wh2 = W_hh + (size_t)(2 * Hd + h) * Hd;
        float a0 = 0, a1 = 0, a2 = 0, a3 = 0, a4 = 0, a5 = 0;
        #pragma unroll 4
        for (int i = lane; i < Hd; i += 32) {
            float xi = s_ix[i], xh = s_hx[i];
            a0 = fmaf(wi0[i], xi, a0);
            a1 = fmaf(wi1[i], xi, a1);
            a2 = fmaf(wi2[i], xi, a2);
            a3 = fmaf(wh0[i], xh, a3);
            a4 = fmaf(wh1[i], xh, a4);
            a5 = fmaf(wh2[i], xh, a5);
        }
        a0 = warp_sum(a0); a1 = warp_sum(a1); a2 = warp_sum(a2);
        a3 = warp_sum(a3); a4 = warp_sum(a4); a5 = warp_sum(a5);
        if (lane == 0) {
            float gr = a0 + b_ih[h] + a3 + b_hh[h];
            float gz = a1 + b_ih[Hd + h] + a4 + b_hh[Hd + h];
            float r = 1.0f / (1.0f + expf(-gr));
            float z = 1.0f / (1.0f + expf(-gz));
            float n = tanhf(a2 + b_ih[2 * Hd + h] + r * (a5 + b_hh[2 * Hd + h]));
            g_hx[wr][b * Hd + h] = (1.0f - z) * n + z * s_hx[h];
        }
    } else {
        if (t == 0) return;
        int fb = blk - 2048;
        int b = fb >> 6;
        int v0 = (fb & 63) << 3;
        int v = v0 + w;
        if (v >= Vout) return;
        const float* fw = fc_w + (size_t)v * Hd;
        const float* hxp = g_hx[rd] + b * Hd;   // ox of step t-1
        const float* sxp = g_sx + b * Hd;       // sx of step t-1
        float acc = 0.0f;
        #pragma unroll 4
        for (int i = lane; i < Hd; i += 32)
            acc = fmaf(hxp[i] + sxp[i], fw[i], acc);
        acc = warp_sum(acc);
        if (lane == 0)
            out[(size_t)b * Lsteps * Vout + (size_t)(t - 1) * Vout + v] = acc + fc_b[v];
    }
}

// ---------------- K2: attention scores ---------------------------------------
// block: one b, 8 consecutive t (1 warp each). conv_w staged in smem.
__global__ void k2_score(
    const float* __restrict__ x, const float* __restrict__ conv_w,
    const float* __restrict__ conv_b, const float* __restrict__ attn_w,
    const float* __restrict__ attn_b, const float* __restrict__ aligns,
    int t, int wr)
{
    __shared__ float s_cw[Hd * KS];   // 30720 B
    __shared__ float s_attw[Hd];
    __shared__ float s_cb[Hd];
    __shared__ float s_hx[Hd];
    __shared__ float s_win[24];       // window [t0-7, t0+14]

    int b  = blockIdx.x / 50;
    int t0 = (blockIdx.x % 50) * 8;
    int tid = threadIdx.x;

    for (int i = tid; i < Hd * KS; i += 256) s_cw[i] = conv_w[i];
    for (int i = tid; i < Hd; i += 256) {
        s_attw[i] = attn_w[i];
        s_cb[i]   = conv_b[i];
        s_hx[i]   = g_hx[wr][b * Hd + i];
    }
    if (tid < 22) {
        int j = t0 - 7 + tid;
        float v = 0.0f;
        if (t > 0 && j >= 0 && j < Tenc)
            v = aligns[(size_t)b * Lsteps * Tenc + (size_t)(t - 1) * Tenc + j];
        s_win[tid] = v;
    }
    __syncthreads();

    int w = tid >> 5, lane = tid & 31;
    int tt = t0 + w;
    const float* xr = x + (size_t)b * Tenc * Hd + (size_t)tt * Hd;
    float acc = 0.0f;

    if (t > 0) {
        #pragma unroll 2
        for (int h = lane; h < Hd; h += 32) {
            float conv = s_cb[h];
            const float* cw = s_cw + h * KS;
            #pragma unroll
            for (int k = 0; k < KS; k++)
                conv = fmaf(cw[k], s_win[w + k], conv);
            float p = xr[h] + s_hx[h] + conv;
            acc = fmaf(fmaxf(p, 0.0f), s_attw[h], acc);
        }
    } else {
        #pragma unroll 4
        for (int h = lane; h < Hd; h += 32) {
            float p = xr[h] + s_hx[h];
            acc = fmaf(fmaxf(p, 0.0f), s_attw[h], acc);
        }
    }
    acc = warp_sum(acc);
    if (lane == 0) g_scores[b * Tenc + tt] = acc + attn_b[0];
}

// ---------------- K3: softmax + context + aligns output ----------------------
// block: one (b, h-tile of 128). Softmax recomputed redundantly per block.
__global__ void k3_ctx(const float* __restrict__ x, float* __restrict__ aligns, int t)
{
    __shared__ float s_a[Tenc];
    __shared__ float s_red[4];

    int b     = blockIdx.x >> 2;
    int htile = blockIdx.x & 3;
    int tid   = threadIdx.x;   // 128
    int lane  = tid & 31, w = tid >> 5;

    float m = -1e30f;
    for (int i = tid; i < Tenc; i += 128) {
        float s = g_scores[b * Tenc + i];
        s_a[i] = s;
        m = fmaxf(m, s);
    }
    #pragma unroll
    for (int o = 16; o; o >>= 1) m = fmaxf(m, __shfl_xor_sync(0xffffffffu, m, o));
    if (lane == 0) s_red[w] = m;
    __syncthreads();
    float bm = fmaxf(fmaxf(s_red[0], s_red[1]), fmaxf(s_red[2], s_red[3]));
    __syncthreads();

    float sum = 0.0f;
    for (int i = tid; i < Tenc; i += 128) {
        float e = expf(s_a[i] - bm);
        s_a[i] = e;
        sum += e;
    }
    sum = warp_sum(sum);
    __syncthreads();           // all s_a writes + bm reads done before s_red reuse
    if (lane == 0) s_red[w] = sum;
    __syncthreads();
    float inv = 1.0f / (s_red[0] + s_red[1] + s_red[2] + s_red[3]);

    int h = (htile << 7) + tid;
    const float* xb = x + (size_t)b * Tenc * Hd + h;
    float acc = 0.0f;
    #pragma unroll 8
    for (int tt = 0; tt < Tenc; tt++)
        acc = fmaf(s_a[tt], xb[(size_t)tt * Hd], acc);
    g_sx[b * Hd + h] = acc * inv;

    if (htile == 0)
        for (int i = tid; i < Tenc; i += 128)
            aligns[(size_t)b * Lsteps * Tenc + (size_t)t * Tenc + i] = s_a[i] * inv;
}

// ---------------- final fc (step 99) -----------------------------------------
__global__ void k_fc_final(const float* __restrict__ fc_w, const float* __restrict__ fc_b,
                           float* __restrict__ out, int step, int rd)
{
    int fb = blockIdx.x;
    int b = fb >> 6;
    int v0 = (fb & 63) << 3;
    int w = threadIdx.x >> 5, lane = threadIdx.x & 31;
    int v = v0 + w;
    if (v >= Vout) return;
    const float* fw = fc_w + (size_t)v * Hd;
    const float* hxp = g_hx[rd] + b * Hd;
    const float* sxp = g_sx + b * Hd;
    float acc = 0.0f;
    #pragma unroll 4
    for (int i = lane; i < Hd; i += 32)
        acc = fmaf(hxp[i] + sxp[i], fw[i], acc);
    acc = warp_sum(acc);
    if (lane == 0)
        out[(size_t)b * Lsteps * Vout + (size_t)step * Vout + v] = acc + fc_b[v];
}

// ---------------- launch ------------------------------------------------------
extern "C" void kernel_launch(void* const* d_in, const int* in_sizes, int n_in,
                              void* d_out, int out_size)
{
    const float* x      = (const float*)d_in[0];
    const int*   y      = (const int*)  d_in[1];
    const float* emb    = (const float*)d_in[2];
    const float* W_ih   = (const float*)d_in[3];
    const float* W_hh   = (const float*)d_in[4];
    const float* b_ih   = (const float*)d_in[5];
    const float* b_hh   = (const float*)d_in[6];
    const float* conv_w = (const float*)d_in[7];
    const float* conv_b = (const float*)d_in[8];
    const float* attn_w = (const float*)d_in[9];
    const float* attn_b = (const float*)d_in[10];
    const float* fc_w   = (const float*)d_in[11];
    const float* fc_b   = (const float*)d_in[12];

    float* out    = (float*)d_out;
    float* aligns = out + (size_t)Bsz * Lsteps * Vout;

    zero_hx_kernel<<<32, 512>>>();

    for (int t = 0; t < Lsteps; t++) {
        int rd = t & 1;
        int wr = rd ^ 1;
        k1_gru_fc<<<4096, 256>>>(y, emb, W_ih, W_hh, b_ih, b_hh, fc_w, fc_b,
                                 out, t, rd, wr);
        k2_score<<<1600, 256>>>(x, conv_w, conv_b, attn_w, attn_b, aligns, t, wr);
        k3_ctx<<<128, 128>>>(x, aligns, t);
    }
    // hx of step 99 lives in buffer ((99&1)^1) = 0
    k_fc_final<<<2048, 256>>>(fc_w, fc_b, out, Lsteps - 1, 0);
}

// round 2
// speedup vs baseline: 1.6376x; 1.6376x over previous
#include <cuda_runtime.h>

#define Bsz 32
#define Tenc 400
#define Hd 512
#define Lsteps 100
#define Vout 511
#define KS 15

// ---------------- persistent state (device globals; no allocation) ----------
__device__ float g_hx[2][Bsz * Hd];   // ping-pong GRU hidden state
__device__ float g_sx[Bsz * Hd];      // attention context
__device__ float g_scores[Bsz * Tenc];

__device__ __forceinline__ float warp_sum(float v) {
    #pragma unroll
    for (int o = 16; o; o >>= 1) v += __shfl_xor_sync(0xffffffffu, v, o);
    return v;
}
__device__ __forceinline__ float warp_max(float v) {
    #pragma unroll
    for (int o = 16; o; o >>= 1) v = fmaxf(v, __shfl_xor_sync(0xffffffffu, v, o));
    return v;
}

__global__ void zero_hx_kernel() {
    g_hx[0][blockIdx.x * blockDim.x + threadIdx.x] = 0.0f;
}

// ---------------- K1: GRU cell (+ fc for previous step) ---------------------
// blocks [0,256): GRU. block = (h-tile of 8, b-tile of 8). warp = 1 h, 8 b.
// blocks [256,512): fc for step t-1. block = (v-tile of 8, b-tile of 8).
__global__ void k1_gru_fc(
    const int* __restrict__ y, const float* __restrict__ emb,
    const float* __restrict__ W_ih, const float* __restrict__ W_hh,
    const float* __restrict__ b_ih, const float* __restrict__ b_hh,
    const float* __restrict__ fc_w, const float* __restrict__ fc_b,
    float* __restrict__ out, int t, int rd, int wr)
{
    __shared__ float s_buf[2][8][Hd];   // [0]=ix / fc-in, [1]=hx
    int blk = blockIdx.x;
    int tid = threadIdx.x;
    int w = tid >> 5, lane = tid & 31;

    if (blk < 256) {
        int ht = blk >> 2, bt = blk & 3;
        int h0 = ht << 3, b0 = bt << 3;
        for (int idx = tid; idx < 8 * Hd; idx += 256) {
            int bb = idx >> 9, i = idx & 511;
            int b = b0 + bb;
            int tok = y[b * 101 + t];
            float v = emb[(size_t)tok * Hd + i];
            if (t > 0) v += g_sx[b * Hd + i];
            s_buf[0][bb][i] = v;
            s_buf[1][bb][i] = g_hx[rd][b * Hd + i];
        }
        __syncthreads();

        int h = h0 + w;
        const float* wi0 = W_ih + (size_t)h * Hd;
        const float* wi1 = W_ih + (size_t)(Hd + h) * Hd;
        const float* wi2 = W_ih + (size_t)(2 * Hd + h) * Hd;
        const float* wh0 = W_hh + (size_t)h * Hd;
        const float* wh1 = W_hh + (size_t)(Hd + h) * Hd;
        const float* wh2 = W_hh + (size_t)(2 * Hd + h) * Hd;

        float acc[6][8];
        #pragma unroll
        for (int g = 0; g < 6; g++)
            #pragma unroll
            for (int bb = 0; bb < 8; bb++) acc[g][bb] = 0.0f;

        for (int i = lane; i < Hd; i += 32) {
            float w0 = wi0[i], w1 = wi1[i], w2 = wi2[i];
            float w3 = wh0[i], w4 = wh1[i], w5 = wh2[i];
            #pragma unroll
            for (int bb = 0; bb < 8; bb++) {
                float xi = s_buf[0][bb][i];
                float xh = s_buf[1][bb][i];
                acc[0][bb] = fmaf(w0, xi, acc[0][bb]);
                acc[1][bb] = fmaf(w1, xi, acc[1][bb]);
                acc[2][bb] = fmaf(w2, xi, acc[2][bb]);
                acc[3][bb] = fmaf(w3, xh, acc[3][bb]);
                acc[4][bb] = fmaf(w4, xh, acc[4][bb]);
                acc[5][bb] = fmaf(w5, xh, acc[5][bb]);
            }
        }
        #pragma unroll
        for (int g = 0; g < 6; g++)
            #pragma unroll
            for (int bb = 0; bb < 8; bb++) acc[g][bb] = warp_sum(acc[g][bb]);

        if (lane < 8) {
            int bb = lane, b = b0 + bb;
            float gr = acc[0][bb] + b_ih[h] + acc[3][bb] + b_hh[h];
            float gz = acc[1][bb] + b_ih[Hd + h] + acc[4][bb] + b_hh[Hd + h];
            float r = 1.0f / (1.0f + expf(-gr));
            float z = 1.0f / (1.0f + expf(-gz));
            float n = tanhf(acc[2][bb] + b_ih[2 * Hd + h] +
                            r * (acc[5][bb] + b_hh[2 * Hd + h]));
            float hp = s_buf[1][bb][h];
            g_hx[wr][b * Hd + h] = (1.0f - z) * n + z * hp;
        }
    } else {
        if (t == 0) return;
        int fb = blk - 256;
        int vt = fb >> 2, bt = fb & 3;
        int b0 = bt << 3;
        for (int idx = tid; idx < 8 * Hd; idx += 256) {
            int bb = idx >> 9, i = idx & 511;
            int b = b0 + bb;
            s_buf[0][bb][i] = g_hx[rd][b * Hd + i] + g_sx[b * Hd + i];
        }
        __syncthreads();

        int v = (vt << 3) + w;
        if (v >= Vout) return;
        const float* fw = fc_w + (size_t)v * Hd;
        float acc[8];
        #pragma unroll
        for (int bb = 0; bb < 8; bb++) acc[bb] = 0.0f;
        for (int i = lane; i < Hd; i += 32) {
            float wv = fw[i];
            #pragma unroll
            for (int bb = 0; bb < 8; bb++)
                acc[bb] = fmaf(wv, s_buf[0][bb][i], acc[bb]);
        }
        #pragma unroll
        for (int bb = 0; bb < 8; bb++) acc[bb] = warp_sum(acc[bb]);
        if (lane < 8) {
            int b = b0 + lane;
            out[(size_t)b * Lsteps * Vout + (size_t)(t - 1) * Vout + v] =
                acc[lane] + fc_b[v];
        }
    }
}

// ---------------- K2: attention scores ---------------------------------------
// block = (b, t-tile of 50). 512 threads = 16 warps; warp c covers h=c*32+lane.
// conv_w row + alignment window live in REGISTERS; smem only for window + reduce.
__global__ void k2_score(
    const float* __restrict__ x, const float* __restrict__ conv_w,
    const float* __restrict__ conv_b, const float* __restrict__ attn_w,
    const float* __restrict__ attn_b, const float* __restrict__ aligns,
    int t, int wr)
{
    __shared__ float s_win[64];
    __shared__ float s_part[16][50];

    int b  = blockIdx.x >> 3;
    int tb = blockIdx.x & 7;
    int T0 = tb * 50;
    int tid = threadIdx.x, c = tid >> 5, lane = tid & 31;
    int h = (c << 5) + lane;

    if (tid < 64) {
        int j = T0 - 7 + tid;
        float v = 0.0f;
        if (t > 0 && j >= 0 && j < Tenc)
            v = aligns[(size_t)b * Lsteps * Tenc + (size_t)(t - 1) * Tenc + j];
        s_win[tid] = v;
    }

    float cw[KS];
    #pragma unroll
    for (int k = 0; k < KS; k++) cw[k] = conv_w[h * KS + k];
    float cbv   = conv_b[h];
    float attwv = attn_w[h];
    float hxv   = g_hx[wr][b * Hd + h];
    __syncthreads();

    const float* xb = x + (size_t)b * Tenc * Hd + h;

    #pragma unroll 1
    for (int tb5 = 0; tb5 < 5; tb5++) {
        int tl0 = tb5 * 10;
        float wreg[24];
        #pragma unroll
        for (int j = 0; j < 24; j++) wreg[j] = s_win[tl0 + j];
        #pragma unroll
        for (int i = 0; i < 10; i++) {
            int tg = T0 + tl0 + i;
            float p = xb[(size_t)tg * Hd] + hxv;
            if (t > 0) {
                float conv = cbv;
                #pragma unroll
                for (int k = 0; k < KS; k++)
                    conv = fmaf(cw[k], wreg[i + k], conv);
                p += conv;
            }
            float part = fmaxf(p, 0.0f) * attwv;
            part = warp_sum(part);
            if (lane == 0) s_part[c][tl0 + i] = part;
        }
    }
    __syncthreads();
    if (tid < 50) {
        float s = 0.0f;
        #pragma unroll
        for (int c2 = 0; c2 < 16; c2++) s += s_part[c2][tid];
        g_scores[b * Tenc + T0 + tid] = s + attn_b[0];
    }
}

// ---------------- K3: softmax + context + aligns output ----------------------
// block = (b, h-tile of 64). 512 threads; 8 groups of 64, each covers 50 t.
__global__ void k3_ctx(const float* __restrict__ x, float* __restrict__ aligns, int t)
{
    __shared__ float s_a[Tenc];
    __shared__ float s_red[16];
    __shared__ float s_part[8][64];

    int b  = blockIdx.x >> 3;
    int ht = blockIdx.x & 7;
    int tid = threadIdx.x, lane = tid & 31, w = tid >> 5;

    float sv = (tid < Tenc) ? g_scores[b * Tenc + tid] : -1e30f;
    float m = warp_max(sv);
    if (lane == 0) s_red[w] = m;
    __syncthreads();
    float bm = -1e30f;
    #pragma unroll
    for (int j = 0; j < 16; j++) bm = fmaxf(bm, s_red[j]);

    float e = (tid < Tenc) ? expf(sv - bm) : 0.0f;
    if (tid < Tenc) s_a[tid] = e;
    float sum = warp_sum(e);
    __syncthreads();          // bm reads + s_a writes complete
    if (lane == 0) s_red[w] = sum;
    __syncthreads();
    float tot = 0.0f;
    #pragma unroll
    for (int j = 0; j < 16; j++) tot += s_red[j];
    float inv = 1.0f / tot;

    int hl = tid & 63, g = tid >> 6;
    int h = (ht << 6) + hl;
    const float* xb = x + (size_t)b * Tenc * Hd + h;
    float acc = 0.0f;
    int t0 = g * 50;
    #pragma unroll 5
    for (int tt = t0; tt < t0 + 50; tt++)
        acc = fmaf(s_a[tt], xb[(size_t)tt * Hd], acc);
    s_part[g][hl] = acc;
    __syncthreads();
    if (g == 0) {
        float a2 = 0.0f;
        #pragma unroll
        for (int gg = 0; gg < 8; gg++) a2 += s_part[gg][hl];
        g_sx[b * Hd + h] = a2 * inv;
    }
    if (ht == 0 && tid < Tenc)
        aligns[(size_t)b * Lsteps * Tenc + (size_t)t * Tenc + tid] = s_a[tid] * inv;
}

// ---------------- final fc (step 99) -----------------------------------------
__global__ void k_fc_final(const float* __restrict__ fc_w, const float* __restrict__ fc_b,
                           float* __restrict__ out, int step, int rd)
{
    __shared__ float s_in[8][Hd];
    int fb = blockIdx.x;
    int vt = fb >> 2, bt = fb & 3;
    int b0 = bt << 3;
    int tid = threadIdx.x, w = tid >> 5, lane = tid & 31;
    for (int idx = tid; idx < 8 * Hd; idx += 256) {
        int bb = idx >> 9, i = idx & 511;
        int b = b0 + bb;
        s_in[bb][i] = g_hx[rd][b * Hd + i] + g_sx[b * Hd + i];
    }
    __syncthreads();
    int v = (vt << 3) + w;
    if (v >= Vout) return;
    const float* fw = fc_w + (size_t)v * Hd;
    float acc[8];
    #pragma unroll
    for (int bb = 0; bb < 8; bb++) acc[bb] = 0.0f;
    for (int i = lane; i < Hd; i += 32) {
        float wv = fw[i];
        #pragma unroll
        for (int bb = 0; bb < 8; bb++) acc[bb] = fmaf(wv, s_in[bb][i], acc[bb]);
    }
    #pragma unroll
    for (int bb = 0; bb < 8; bb++) acc[bb] = warp_sum(acc[bb]);
    if (lane < 8) {
        int b = b0 + lane;
        out[(size_t)b * Lsteps * Vout + (size_t)step * Vout + v] = acc[lane] + fc_b[v];
    }
}

// ---------------- launch ------------------------------------------------------
extern "C" void kernel_launch(void* const* d_in, const int* in_sizes, int n_in,
                              void* d_out, int out_size)
{
    const float* x      = (const float*)d_in[0];
    const int*   y      = (const int*)  d_in[1];
    const float* emb    = (const float*)d_in[2];
    const float* W_ih   = (const float*)d_in[3];
    const float* W_hh   = (const float*)d_in[4];
    const float* b_ih   = (const float*)d_in[5];
    const float* b_hh   = (const float*)d_in[6];
    const float* conv_w = (const float*)d_in[7];
    const float* conv_b = (const float*)d_in[8];
    const float* attn_w = (const float*)d_in[9];
    const float* attn_b = (const float*)d_in[10];
    const float* fc_w   = (const float*)d_in[11];
    const float* fc_b   = (const float*)d_in[12];

    float* out    = (float*)d_out;
    float* aligns = out + (size_t)Bsz * Lsteps * Vout;

    zero_hx_kernel<<<32, 512>>>();

    for (int t = 0; t < Lsteps; t++) {
        int rd = t & 1;
        int wr = rd ^ 1;
        k1_gru_fc<<<512, 256>>>(y, emb, W_ih, W_hh, b_ih, b_hh, fc_w, fc_b,
                                out, t, rd, wr);
        k2_score<<<256, 512>>>(x, conv_w, conv_b, attn_w, attn_b, aligns, t, wr);
        k3_ctx<<<256, 512>>>(x, aligns, t);
    }
    // hx of step 99 lives in buffer 0
    k_fc_final<<<256, 256>>>(fc_w, fc_b, out, Lsteps - 1, 0);
}